// round 14
// baseline (speedup 1.0000x reference)
#include <cuda_runtime.h>
#include <math.h>
#include <stdint.h>

#define NN 1024
#define FD 32
#define ED 20
#define JT 64            // j per tile
#define NT (NN / JT)     // 16 tiles
#define NSTAGE 4

typedef unsigned long long ull;

// Precomputed per-j packs (verified R9/R12):
//  g_lv[j*32+f] = (La*V0, La*V1, La*V2, Lb)
//  g_lc[j*32+f] = Lc
__device__ float4 g_lv[NN * 32];
__device__ float  g_lc[NN * 32];

// ---- f32x2 helpers (verified R8/R12) ----
__device__ __forceinline__ ull ffma2(ull a, ull b, ull c) {
    ull d; asm("fma.rn.f32x2 %0, %1, %2, %3;" : "=l"(d) : "l"(a), "l"(b), "l"(c)); return d;
}
__device__ __forceinline__ ull pack2(float lo, float hi) {
    ull r; asm("mov.b64 %0, {%1, %2};" : "=l"(r) : "f"(lo), "f"(hi)); return r;
}
__device__ __forceinline__ float f2lo(ull p) { return __int_as_float((int)(unsigned)p); }
__device__ __forceinline__ float f2hi(ull p) { return __int_as_float((int)(p >> 32)); }

// ---- cp.async helpers ----
__device__ __forceinline__ void cp16(uint32_t dst, const void* src) {
    asm volatile("cp.async.ca.shared.global [%0], [%1], 16;" :: "r"(dst), "l"(src));
}
#define CP_COMMIT() asm volatile("cp.async.commit_group;" ::: "memory")
#define CP_WAIT2()  asm volatile("cp.async.wait_group 2;" ::: "memory")

// Per-tile staged buffer, float4 units (verified R12):
// [0,320)   X     (64 j x 20 floats)
// [320,368) dir   (64 j x 3 floats)
// [368,384) mask  (64 floats)
#define TB_F4 384

// ---------------------------------------------------------------------------
// Kernel 1: per-node msg_left MLP -> packed LV / Lc.  grid=NN, block=96.
// ---------------------------------------------------------------------------
__global__ void left_kernel(const float* __restrict__ scalar,
                            const float* __restrict__ vector,
                            const float* __restrict__ w1, const float* __restrict__ b1,
                            const float* __restrict__ w2, const float* __restrict__ b2) {
    int j = blockIdx.x;
    int t = threadIdx.x;
    __shared__ float ss[FD];
    __shared__ float sh[FD];
    __shared__ float sL[96];
    if (t < FD) ss[t] = scalar[j * FD + t];
    __syncthreads();
    if (t < FD) {
        float acc = b1[t];
#pragma unroll
        for (int k = 0; k < FD; k++) acc += ss[k] * w1[k * FD + t];
        sh[t] = acc / (1.0f + expf(-acc));   // silu
    }
    __syncthreads();
    float acc = b2[t];
#pragma unroll
    for (int k = 0; k < FD; k++) acc += sh[k] * w2[k * 96 + t];
    sL[t] = acc;
    __syncthreads();
    if (t < 32) {
        float La = sL[t], Lb = sL[32 + t], Lc = sL[64 + t];
        float v0 = vector[j * 96 + t];
        float v1 = vector[j * 96 + 32 + t];
        float v2 = vector[j * 96 + 64 + t];
        g_lv[j * 32 + t] = make_float4(La * v0, La * v1, La * v2, Lb);
        g_lc[j * 32 + t] = Lc;
    }
}

// ---------------------------------------------------------------------------
// Stage one 64-j tile (X, dir, mask) via cp.async. 384 float4, 256 threads. (R12)
// ---------------------------------------------------------------------------
__device__ __forceinline__ void stage_tile(
        float4* buf, int j0, int tid,
        const float* Xrow, const float* Drow, const float* Mrow) {
    uint32_t dst = (uint32_t)__cvta_generic_to_shared(buf);
    cp16(dst + (uint32_t)tid * 16u, (const float4*)(Xrow + j0 * ED) + tid);
    int k2 = tid + 256;
    if (k2 < TB_F4) {
        const float4* s;
        if (k2 < 320)      s = (const float4*)(Xrow + j0 * ED) + k2;
        else if (k2 < 368) s = (const float4*)(Drow + j0 * 3) + (k2 - 320);
        else               s = (const float4*)(Mrow + j0) + (k2 - 368);
        cp16(dst + (uint32_t)k2 * 16u, s);
    }
}

// ---------------------------------------------------------------------------
// Kernel 2: warp-specialized fused message + update, one CTA per node i.
// block = 256, 3 CTAs/SM (<=85 regs).
// Warps 0-3: components a+b (40 weight regs). Warps 4-7: component c (20 regs).
// Each warp covers 16 j per 64-j tile for its component set.
// ---------------------------------------------------------------------------
__global__ void __launch_bounds__(256, 3)
main_kernel(const float* __restrict__ scalar, const float* __restrict__ vector,
            const float* __restrict__ expansion, const float* __restrict__ direction,
            const float* __restrict__ mask,
            const float* __restrict__ mRw, const float* __restrict__ mRb,
            const float* __restrict__ uRw1, const float* __restrict__ uRb1,
            const float* __restrict__ uRw2, const float* __restrict__ uRb2,
            const float* __restrict__ Uw, const float* __restrict__ Vw,
            float* __restrict__ out) {
    int i = blockIdx.x;
    int tid = threadIdx.x;
    int warp = tid >> 5, lane = tid & 31;
    const int wtype = warp >> 2;       // 0 = a+b warps, 1 = c warps
    const int wsub  = warp & 3;        // j-range index within type

    __shared__ __align__(16) float4 smBuf[NSTAGE][TB_F4];   // 24 KB
    __shared__ float red[8][4][32];
    __shared__ float ds[32], dv[96];
    __shared__ float s_new[32], v_new[96], lu[96], ru[96], feats[64], hbuf[32], og[96];

    // Weights for this warp's component set (e-paired, R8/R12 layout).
    // wtype 0: w1 = wA, w2 = wB.   wtype 1: w1 = wC, w2 unused.
    ull w1[ED / 2], w2[ED / 2];
    ull bias1, bias2;
    if (wtype == 0) {
#pragma unroll
        for (int q = 0; q < ED / 2; q++) {
            w1[q] = pack2(mRw[(2 * q) * 96 + lane],      mRw[(2 * q + 1) * 96 + lane]);
            w2[q] = pack2(mRw[(2 * q) * 96 + 32 + lane], mRw[(2 * q + 1) * 96 + 32 + lane]);
        }
        bias1 = pack2(mRb[lane], 0.f);
        bias2 = pack2(mRb[32 + lane], 0.f);
    } else {
#pragma unroll
        for (int q = 0; q < ED / 2; q++) {
            w1[q] = pack2(mRw[(2 * q) * 96 + 64 + lane], mRw[(2 * q + 1) * 96 + 64 + lane]);
            w2[q] = 0ULL;
        }
        bias1 = pack2(mRb[64 + lane], 0.f);
        bias2 = 0ULL;
    }

    const float* Xrow = expansion + (size_t)i * NN * ED;
    const float* Mrow = mask + (size_t)i * NN;
    const float* Drow = direction + (size_t)i * NN * 3;

    float acc_s = 0.f, acc_v0 = 0.f, acc_v1 = 0.f, acc_v2 = 0.f;

    // prologue: stage tiles 0..2 (3 groups in flight)
    stage_tile(smBuf[0], 0 * JT, tid, Xrow, Drow, Mrow); CP_COMMIT();
    stage_tile(smBuf[1], 1 * JT, tid, Xrow, Drow, Mrow); CP_COMMIT();
    stage_tile(smBuf[2], 2 * JT, tid, Xrow, Drow, Mrow); CP_COMMIT();

    for (int t = 0; t < NT; t++) {
        CP_WAIT2();
        __syncthreads();
        if (t + 3 < NT)
            stage_tile(smBuf[(t + 3) & (NSTAGE - 1)], (t + 3) * JT, tid, Xrow, Drow, Mrow);
        CP_COMMIT();

        const float* X  = (const float*)(smBuf[t & (NSTAGE - 1)]);
        const float* Dr = (const float*)(smBuf[t & (NSTAGE - 1)] + 320);
        const float* M  = (const float*)(smBuf[t & (NSTAGE - 1)] + 368);
        const int jbase = wsub * 16;

        if (wtype == 0) {
            // ---- a+b warps: 16 j, matvec(a,b) + LV epilogue ----
#pragma unroll 2
            for (int u = 0; u < 16; u++) {
                const int jj = jbase + u;
                const int j = t * JT + jj;

                const ulonglong2* xp = (const ulonglong2*)(X + jj * ED);
                ull pa2 = bias1, pb2 = bias2;
#pragma unroll
                for (int q5 = 0; q5 < 5; q5++) {
                    ulonglong2 xx = xp[q5];
                    pa2 = ffma2(xx.x, w1[2 * q5], pa2);
                    pb2 = ffma2(xx.x, w2[2 * q5], pb2);
                    pa2 = ffma2(xx.y, w1[2 * q5 + 1], pa2);
                    pb2 = ffma2(xx.y, w2[2 * q5 + 1], pb2);
                }
                float ra = f2lo(pa2) + f2hi(pa2);
                float rb = f2lo(pb2) + f2hi(pb2);

                float4 LVv = g_lv[j * 32 + lane];   // LDG.128 coalesced (L2)
                float  m   = M[jj];                 // LDS broadcast

                float ta = m * ra;
                acc_v0 = fmaf(ta, LVv.x, acc_v0);
                acc_v1 = fmaf(ta, LVv.y, acc_v1);
                acc_v2 = fmaf(ta, LVv.z, acc_v2);
                acc_s  = fmaf(m * rb, LVv.w, acc_s);
            }
        } else {
            // ---- c warps: 16 j, matvec(c) + direction epilogue ----
#pragma unroll 4
            for (int u = 0; u < 16; u++) {
                const int jj = jbase + u;
                const int j = t * JT + jj;

                const ulonglong2* xp = (const ulonglong2*)(X + jj * ED);
                ull pc2 = bias1;
#pragma unroll
                for (int q5 = 0; q5 < 5; q5++) {
                    ulonglong2 xx = xp[q5];
                    pc2 = ffma2(xx.x, w1[2 * q5], pc2);
                    pc2 = ffma2(xx.y, w1[2 * q5 + 1], pc2);
                }
                float rc = f2lo(pc2) + f2hi(pc2);

                float lc = g_lc[j * 32 + lane];     // LDG.32 coalesced (L2)
                float m  = M[jj];
                float d0 = Dr[jj * 3], d1 = Dr[jj * 3 + 1], d2 = Dr[jj * 3 + 2];

                float tc = (m * rc) * lc;
                acc_v0 = fmaf(tc, d0, acc_v0);
                acc_v1 = fmaf(tc, d1, acc_v1);
                acc_v2 = fmaf(tc, d2, acc_v2);
            }
        }
    }

    // cross-warp reduction (c warps contribute acc_s = 0)
    red[warp][0][lane] = acc_s;
    red[warp][1][lane] = acc_v0;
    red[warp][2][lane] = acc_v1;
    red[warp][3][lane] = acc_v2;
    __syncthreads();
    if (tid < 128) {
        int a = tid >> 5, f = tid & 31;
        float s = 0.f;
#pragma unroll
        for (int w = 0; w < 8; w++) s += red[w][a][f];
        if (a == 0) ds[f] = s; else dv[(a - 1) * 32 + f] = s;
    }
    __syncthreads();

    // ---- update phase (verified R2/R8/R12) ----
    if (tid < 32) s_new[tid] = scalar[i * 32 + tid] + ds[tid];
    if (tid < 96) v_new[tid] = vector[i * 96 + tid] + dv[tid];
    __syncthreads();

    if (tid < 96) {  // left = v_new @ U_w, right = v_new @ V_w
        int d = tid >> 5, f = tid & 31;
        float a1 = 0.f, a2 = 0.f;
#pragma unroll
        for (int k = 0; k < 32; k++) {
            float v = v_new[d * 32 + k];
            a1 += v * Uw[k * 32 + f];
            a2 += v * Vw[k * 32 + f];
        }
        lu[tid] = a1;
        ru[tid] = a2;
    }
    __syncthreads();
    if (tid < 32) {
        float r0 = ru[tid], r1 = ru[32 + tid], r2 = ru[64 + tid];
        feats[tid] = s_new[tid];
        feats[32 + tid] = sqrtf(r0 * r0 + r1 * r1 + r2 * r2);
    }
    __syncthreads();
    if (tid < 32) {
        float acc = uRb1[tid];
#pragma unroll
        for (int k = 0; k < 64; k++) acc += feats[k] * uRw1[k * 32 + tid];
        hbuf[tid] = acc / (1.0f + expf(-acc));   // silu
    }
    __syncthreads();
    if (tid < 96) {
        float acc = uRb2[tid];
#pragma unroll
        for (int k = 0; k < 32; k++) acc += hbuf[k] * uRw2[k * 96 + tid];
        og[tid] = acc;
    }
    __syncthreads();
    if (tid < 32) {  // scalar out: s_new + inner*b + c
        float inner = lu[tid] * ru[tid] + lu[32 + tid] * ru[32 + tid] + lu[64 + tid] * ru[64 + tid];
        out[i * 32 + tid] = s_new[tid] + inner * og[32 + tid] + og[64 + tid];
    }
    if (tid < 96) {  // vector out: v_new + a*left
        out[NN * 32 + i * 96 + tid] = v_new[tid] + og[tid & 31] * lu[tid];
    }
}

// ---------------------------------------------------------------------------
// launch
// inputs (metadata order): 0 scalar, 1 vector, 2 expansion, 3 direction, 4 mask,
// 5 mL_w1, 6 mL_b1, 7 mL_w2, 8 mL_b2, 9 mR_w, 10 mR_b,
// 11 uR_w1, 12 uR_b1, 13 uR_w2, 14 uR_b2, 15 U_w, 16 V_w
// output: [scalar_out (1024*32) | vector_out (1024*96)] fp32
// ---------------------------------------------------------------------------
extern "C" void kernel_launch(void* const* d_in, const int* in_sizes, int n_in,
                              void* d_out, int out_size) {
    const float* scalar    = (const float*)d_in[0];
    const float* vector    = (const float*)d_in[1];
    const float* expansion = (const float*)d_in[2];
    const float* direction = (const float*)d_in[3];
    const float* mask      = (const float*)d_in[4];
    const float* mL_w1 = (const float*)d_in[5];
    const float* mL_b1 = (const float*)d_in[6];
    const float* mL_w2 = (const float*)d_in[7];
    const float* mL_b2 = (const float*)d_in[8];
    const float* mR_w  = (const float*)d_in[9];
    const float* mR_b  = (const float*)d_in[10];
    const float* uR_w1 = (const float*)d_in[11];
    const float* uR_b1 = (const float*)d_in[12];
    const float* uR_w2 = (const float*)d_in[13];
    const float* uR_b2 = (const float*)d_in[14];
    const float* U_w   = (const float*)d_in[15];
    const float* V_w   = (const float*)d_in[16];
    float* out = (float*)d_out;

    left_kernel<<<NN, 96>>>(scalar, vector, mL_w1, mL_b1, mL_w2, mL_b2);
    main_kernel<<<NN, 256>>>(scalar, vector, expansion, direction, mask,
                             mR_w, mR_b, uR_w1, uR_b1, uR_w2, uR_b2, U_w, V_w, out);
}

// round 15
// speedup vs baseline: 1.5657x; 1.5657x over previous
#include <cuda_runtime.h>
#include <math.h>
#include <stdint.h>

#define NN 1024
#define FD 32
#define ED 20
#define JT 64            // j per tile
#define NT (NN / JT)     // 16 tiles
#define NSTAGE 4

typedef unsigned long long ull;

// Precomputed per-j packs (verified R9/R12):
//  g_lv[j*32+f] = (La*V0, La*V1, La*V2, Lb)
//  g_lc[j*32+f] = Lc
__device__ float4 g_lv[NN * 32];
__device__ float  g_lc[NN * 32];

// ---- f32x2 helpers (verified R8/R12) ----
__device__ __forceinline__ ull ffma2(ull a, ull b, ull c) {
    ull d; asm("fma.rn.f32x2 %0, %1, %2, %3;" : "=l"(d) : "l"(a), "l"(b), "l"(c)); return d;
}
__device__ __forceinline__ ull pack2(float lo, float hi) {
    ull r; asm("mov.b64 %0, {%1, %2};" : "=l"(r) : "f"(lo), "f"(hi)); return r;
}
__device__ __forceinline__ float f2lo(ull p) { return __int_as_float((int)(unsigned)p); }
__device__ __forceinline__ float f2hi(ull p) { return __int_as_float((int)(p >> 32)); }

// ---- cp.async helpers ----
__device__ __forceinline__ void cp16(uint32_t dst, const void* src) {
    asm volatile("cp.async.ca.shared.global [%0], [%1], 16;" :: "r"(dst), "l"(src));
}
#define CP_COMMIT() asm volatile("cp.async.commit_group;" ::: "memory")
#define CP_WAIT2()  asm volatile("cp.async.wait_group 2;" ::: "memory")

// Per-tile staged buffer, float4 units (verified R12):
// [0,320)   X     (64 j x 20 floats)
// [320,368) dir   (64 j x 3 floats)
// [368,384) mask  (64 floats)
#define TB_F4 384

// ---------------------------------------------------------------------------
// Kernel 1: per-node msg_left MLP -> packed LV / Lc.  grid=NN, block=96.
// ---------------------------------------------------------------------------
__global__ void left_kernel(const float* __restrict__ scalar,
                            const float* __restrict__ vector,
                            const float* __restrict__ w1, const float* __restrict__ b1,
                            const float* __restrict__ w2, const float* __restrict__ b2) {
    int j = blockIdx.x;
    int t = threadIdx.x;
    __shared__ float ss[FD];
    __shared__ float sh[FD];
    __shared__ float sL[96];
    if (t < FD) ss[t] = scalar[j * FD + t];
    __syncthreads();
    if (t < FD) {
        float acc = b1[t];
#pragma unroll
        for (int k = 0; k < FD; k++) acc += ss[k] * w1[k * FD + t];
        sh[t] = acc / (1.0f + expf(-acc));   // silu
    }
    __syncthreads();
    float acc = b2[t];
#pragma unroll
    for (int k = 0; k < FD; k++) acc += sh[k] * w2[k * 96 + t];
    sL[t] = acc;
    __syncthreads();
    if (t < 32) {
        float La = sL[t], Lb = sL[32 + t], Lc = sL[64 + t];
        float v0 = vector[j * 96 + t];
        float v1 = vector[j * 96 + 32 + t];
        float v2 = vector[j * 96 + 64 + t];
        g_lv[j * 32 + t] = make_float4(La * v0, La * v1, La * v2, Lb);
        g_lc[j * 32 + t] = Lc;
    }
}

// ---------------------------------------------------------------------------
// Stage one 64-j tile (X, dir, mask) via cp.async. 384 float4, 256 threads. (R12)
// ---------------------------------------------------------------------------
__device__ __forceinline__ void stage_tile(
        float4* buf, int j0, int tid,
        const float* Xrow, const float* Drow, const float* Mrow) {
    uint32_t dst = (uint32_t)__cvta_generic_to_shared(buf);
    cp16(dst + (uint32_t)tid * 16u, (const float4*)(Xrow + j0 * ED) + tid);
    int k2 = tid + 256;
    if (k2 < TB_F4) {
        const float4* s;
        if (k2 < 320)      s = (const float4*)(Xrow + j0 * ED) + k2;
        else if (k2 < 368) s = (const float4*)(Drow + j0 * 3) + (k2 - 320);
        else               s = (const float4*)(Mrow + j0) + (k2 - 368);
        cp16(dst + (uint32_t)k2 * 16u, s);
    }
}

// ---------------------------------------------------------------------------
// Kernel 2: fused message-reduction + update, one CTA per node i.  (R12 base)
// block = 256 (8 warps), 2-CTA occupancy. Each warp: 8 j per 64-j tile.
// NEW vs R12: LV/Lc software-pipelined 1 iteration ahead inside the
// fully-unrolled 8-j loop, so each LDG's latency is covered by a matvec.
// ---------------------------------------------------------------------------
__global__ void __launch_bounds__(256, 2)
main_kernel(const float* __restrict__ scalar, const float* __restrict__ vector,
            const float* __restrict__ expansion, const float* __restrict__ direction,
            const float* __restrict__ mask,
            const float* __restrict__ mRw, const float* __restrict__ mRb,
            const float* __restrict__ uRw1, const float* __restrict__ uRb1,
            const float* __restrict__ uRw2, const float* __restrict__ uRb2,
            const float* __restrict__ Uw, const float* __restrict__ Vw,
            float* __restrict__ out) {
    int i = blockIdx.x;
    int tid = threadIdx.x;
    int warp = tid >> 5, lane = tid & 31;

    __shared__ __align__(16) float4 smBuf[NSTAGE][TB_F4];   // 24 KB
    __shared__ float red[8][4][32];
    __shared__ float ds[32], dv[96];
    __shared__ float s_new[32], v_new[96], lu[96], ru[96], feats[64], hbuf[32], og[96];

    // mR_w columns owned by this lane, packed as e-pairs (60 regs). (R8/R12)
    ull wA[ED / 2], wB[ED / 2], wC[ED / 2];
#pragma unroll
    for (int q = 0; q < ED / 2; q++) {
        wA[q] = pack2(mRw[(2 * q) * 96 + lane],      mRw[(2 * q + 1) * 96 + lane]);
        wB[q] = pack2(mRw[(2 * q) * 96 + 32 + lane], mRw[(2 * q + 1) * 96 + 32 + lane]);
        wC[q] = pack2(mRw[(2 * q) * 96 + 64 + lane], mRw[(2 * q + 1) * 96 + 64 + lane]);
    }
    const ull biasA = pack2(mRb[lane], 0.f);
    const ull biasB = pack2(mRb[32 + lane], 0.f);
    const ull biasC = pack2(mRb[64 + lane], 0.f);

    const float* Xrow = expansion + (size_t)i * NN * ED;
    const float* Mrow = mask + (size_t)i * NN;
    const float* Drow = direction + (size_t)i * NN * 3;

    float acc_s = 0.f, acc_v0 = 0.f, acc_v1 = 0.f, acc_v2 = 0.f;

    // prologue: stage tiles 0..2 (3 groups in flight)
    stage_tile(smBuf[0], 0 * JT, tid, Xrow, Drow, Mrow); CP_COMMIT();
    stage_tile(smBuf[1], 1 * JT, tid, Xrow, Drow, Mrow); CP_COMMIT();
    stage_tile(smBuf[2], 2 * JT, tid, Xrow, Drow, Mrow); CP_COMMIT();

    for (int t = 0; t < NT; t++) {
        CP_WAIT2();        // tile t's group complete (<=2 newer pending)
        __syncthreads();   // visible to all; previous tile's compute done
        if (t + 3 < NT)
            stage_tile(smBuf[(t + 3) & (NSTAGE - 1)], (t + 3) * JT, tid, Xrow, Drow, Mrow);
        CP_COMMIT();       // one commit per iteration keeps group accounting in step

        const float* X  = (const float*)(smBuf[t & (NSTAGE - 1)]);
        const float* Dr = (const float*)(smBuf[t & (NSTAGE - 1)] + 320);
        const float* M  = (const float*)(smBuf[t & (NSTAGE - 1)] + 368);

        // ---- 8 j per warp, LV/Lc pipelined one iteration ahead ----
        const int jb = t * JT + warp * 8;           // first global j for this warp
        float4 LVn = g_lv[jb * 32 + lane];
        float  lcn = g_lc[jb * 32 + lane];

#pragma unroll
        for (int u = 0; u < 8; u++) {
            const int jj = warp * 8 + u;

            // consume prefetched values, immediately issue next iteration's loads
            float4 LVv = LVn;
            float  lc  = lcn;
            if (u < 7) {
                LVn = g_lv[(jb + u + 1) * 32 + lane];   // LDG.128, ~100+ slots to use
                lcn = g_lc[(jb + u + 1) * 32 + lane];   // LDG.32
            }

            // 20->96 matvec: 5 LDS.128 broadcasts + 30 FFMA2 + 3 FADD (R8/R12)
            const ulonglong2* xp = (const ulonglong2*)(X + jj * ED);
            ull pa2 = biasA, pb2 = biasB, pc2 = biasC;
#pragma unroll
            for (int q5 = 0; q5 < 5; q5++) {
                ulonglong2 xx = xp[q5];
                pa2 = ffma2(xx.x, wA[2 * q5], pa2);
                pb2 = ffma2(xx.x, wB[2 * q5], pb2);
                pc2 = ffma2(xx.x, wC[2 * q5], pc2);
                pa2 = ffma2(xx.y, wA[2 * q5 + 1], pa2);
                pb2 = ffma2(xx.y, wB[2 * q5 + 1], pb2);
                pc2 = ffma2(xx.y, wC[2 * q5 + 1], pc2);
            }
            float ra = f2lo(pa2) + f2hi(pa2);
            float rb = f2lo(pb2) + f2hi(pb2);
            float rc = f2lo(pc2) + f2hi(pc2);

            float m  = M[jj];                 // LDS broadcast
            float d0 = Dr[jj * 3], d1 = Dr[jj * 3 + 1], d2 = Dr[jj * 3 + 2];

            float ta = m * ra;
            acc_v0 = fmaf(ta, LVv.x, acc_v0);
            acc_v1 = fmaf(ta, LVv.y, acc_v1);
            acc_v2 = fmaf(ta, LVv.z, acc_v2);
            acc_s  = fmaf(m * rb, LVv.w, acc_s);
            float tc = (m * rc) * lc;
            acc_v0 = fmaf(tc, d0, acc_v0);
            acc_v1 = fmaf(tc, d1, acc_v1);
            acc_v2 = fmaf(tc, d2, acc_v2);
        }
    }

    // cross-warp reduction
    red[warp][0][lane] = acc_s;
    red[warp][1][lane] = acc_v0;
    red[warp][2][lane] = acc_v1;
    red[warp][3][lane] = acc_v2;
    __syncthreads();
    if (tid < 128) {
        int a = tid >> 5, f = tid & 31;
        float s = 0.f;
#pragma unroll
        for (int w = 0; w < 8; w++) s += red[w][a][f];
        if (a == 0) ds[f] = s; else dv[(a - 1) * 32 + f] = s;
    }
    __syncthreads();

    // ---- update phase (verified R2/R8/R12) ----
    if (tid < 32) s_new[tid] = scalar[i * 32 + tid] + ds[tid];
    if (tid < 96) v_new[tid] = vector[i * 96 + tid] + dv[tid];
    __syncthreads();

    if (tid < 96) {  // left = v_new @ U_w, right = v_new @ V_w
        int d = tid >> 5, f = tid & 31;
        float a1 = 0.f, a2 = 0.f;
#pragma unroll
        for (int k = 0; k < 32; k++) {
            float v = v_new[d * 32 + k];
            a1 += v * Uw[k * 32 + f];
            a2 += v * Vw[k * 32 + f];
        }
        lu[tid] = a1;
        ru[tid] = a2;
    }
    __syncthreads();
    if (tid < 32) {
        float r0 = ru[tid], r1 = ru[32 + tid], r2 = ru[64 + tid];
        feats[tid] = s_new[tid];
        feats[32 + tid] = sqrtf(r0 * r0 + r1 * r1 + r2 * r2);
    }
    __syncthreads();
    if (tid < 32) {
        float acc = uRb1[tid];
#pragma unroll
        for (int k = 0; k < 64; k++) acc += feats[k] * uRw1[k * 32 + tid];
        hbuf[tid] = acc / (1.0f + expf(-acc));   // silu
    }
    __syncthreads();
    if (tid < 96) {
        float acc = uRb2[tid];
#pragma unroll
        for (int k = 0; k < 32; k++) acc += hbuf[k] * uRw2[k * 96 + tid];
        og[tid] = acc;
    }
    __syncthreads();
    if (tid < 32) {  // scalar out: s_new + inner*b + c
        float inner = lu[tid] * ru[tid] + lu[32 + tid] * ru[32 + tid] + lu[64 + tid] * ru[64 + tid];
        out[i * 32 + tid] = s_new[tid] + inner * og[32 + tid] + og[64 + tid];
    }
    if (tid < 96) {  // vector out: v_new + a*left
        out[NN * 32 + i * 96 + tid] = v_new[tid] + og[tid & 31] * lu[tid];
    }
}

// ---------------------------------------------------------------------------
// launch
// inputs (metadata order): 0 scalar, 1 vector, 2 expansion, 3 direction, 4 mask,
// 5 mL_w1, 6 mL_b1, 7 mL_w2, 8 mL_b2, 9 mR_w, 10 mR_b,
// 11 uR_w1, 12 uR_b1, 13 uR_w2, 14 uR_b2, 15 U_w, 16 V_w
// output: [scalar_out (1024*32) | vector_out (1024*96)] fp32
// ---------------------------------------------------------------------------
extern "C" void kernel_launch(void* const* d_in, const int* in_sizes, int n_in,
                              void* d_out, int out_size) {
    const float* scalar    = (const float*)d_in[0];
    const float* vector    = (const float*)d_in[1];
    const float* expansion = (const float*)d_in[2];
    const float* direction = (const float*)d_in[3];
    const float* mask      = (const float*)d_in[4];
    const float* mL_w1 = (const float*)d_in[5];
    const float* mL_b1 = (const float*)d_in[6];
    const float* mL_w2 = (const float*)d_in[7];
    const float* mL_b2 = (const float*)d_in[8];
    const float* mR_w  = (const float*)d_in[9];
    const float* mR_b  = (const float*)d_in[10];
    const float* uR_w1 = (const float*)d_in[11];
    const float* uR_b1 = (const float*)d_in[12];
    const float* uR_w2 = (const float*)d_in[13];
    const float* uR_b2 = (const float*)d_in[14];
    const float* U_w   = (const float*)d_in[15];
    const float* V_w   = (const float*)d_in[16];
    float* out = (float*)d_out;

    left_kernel<<<NN, 96>>>(scalar, vector, mL_w1, mL_b1, mL_w2, mL_b2);
    main_kernel<<<NN, 256>>>(scalar, vector, expansion, direction, mask,
                             mR_w, mR_b, uR_w1, uR_b1, uR_w2, uR_b2, U_w, V_w, out);
}